// round 15
// baseline (speedup 1.0000x reference)
#include <cuda_runtime.h>
#include <cuda_bf16.h>
#include <cstdint>

#define N_ROWS 262144
#define D_DIM  768
#define K_DIM  1024

// ---------------- device scratch ----------------
__device__ float         g_ct [K_DIM * D_DIM];     // fp32 C^T (gather + exact fixup)
__device__ __nv_bfloat16 g_bhi[K_DIM * D_DIM];     // bf16 C^T (K-major)
__device__ __nv_bfloat16 g_xb [(size_t)N_ROWS * D_DIM];  // bf16 x (402 MB)
__device__ int           g_idx[N_ROWS];
__device__ int           g_fix_count;
__device__ int           g_fix_rows[32768];

// ---------------- helpers ----------------
__device__ __forceinline__ uint32_t smem_u32(const void* p) {
    uint32_t a;
    asm("{ .reg .u64 t; cvta.to.shared.u64 t, %1; cvt.u32.u64 %0, t; }" : "=r"(a) : "l"(p));
    return a;
}
__device__ __forceinline__ void cpa16(uint32_t dst, const void* src) {
    asm volatile("{ .reg .u64 p; cvta.to.global.u64 p, %1; cp.async.cg.shared.global [%0], [p], 16; }"
                 :: "r"(dst), "l"(src));
}
__device__ __forceinline__ void ldsm4(uint32_t* r, uint32_t a) {
    asm volatile("ldmatrix.sync.aligned.m8n8.x4.shared.b16 {%0,%1,%2,%3}, [%4];"
                 : "=r"(r[0]), "=r"(r[1]), "=r"(r[2]), "=r"(r[3]) : "r"(a));
}
__device__ __forceinline__ void mma16816(float* c, const uint32_t* a, uint32_t b0, uint32_t b1) {
    asm volatile("mma.sync.aligned.m16n8k16.row.col.f32.bf16.bf16.f32 "
                 "{%0,%1,%2,%3},{%4,%5,%6,%7},{%8,%9},{%0,%1,%2,%3};"
                 : "+f"(c[0]), "+f"(c[1]), "+f"(c[2]), "+f"(c[3])
                 : "r"(a[0]), "r"(a[1]), "r"(a[2]), "r"(a[3]), "r"(b0), "r"(b1));
}

#define FIX_THRESH 0.87f
#define FIX_CAP    32768

// ---------------- smem layout (dynamic) ----------------
// Stage = TWO proven 80B-row sub-tiles (d-chunk 64): sub-stage h at
// h*30720, each {A 128x80B, B 256x80B} with R14's exact addressing.
#define SM_CN   0        // 1024 f32
#define SM_PB   4096     // 4 x 128 f32 partials
#define SM_PS   6144
#define SM_PI   8192
#define SM_BEST 10240
#define SM_SEC  10752
#define SM_BIDX 11264
#define SM_STG  12288
#define HALF_BYTES 30720
#define STG_BYTES  61440
#define A_HI 0
#define B_HI 10240
#define SMEM_TOTAL (12288 + 2 * 61440)   // 135168

// ---------------------------------------------------------------------------
// Kernel 0a: C -> fp32 C^T + bf16 C^T; zero fixup counter
// ---------------------------------------------------------------------------
__global__ void k_prep(const float* __restrict__ C) {
    int idx = blockIdx.x * 256 + threadIdx.x;    // idx = d*1024 + k
    if (idx == 0) g_fix_count = 0;
    int d = idx >> 10, k = idx & 1023;
    float v = C[idx];
    size_t o = (size_t)k * D_DIM + d;
    g_ct[o] = v; g_bhi[o] = __float2bfloat16_rn(v);
}

// ---------------------------------------------------------------------------
// Kernel 0b: x -> bf16 (one-time)
// ---------------------------------------------------------------------------
__global__ void k_prepx(const float* __restrict__ x) {
    size_t i = ((size_t)blockIdx.x * 256 + threadIdx.x) * 4;
    float4 v = *(const float4*)(x + i);
    __nv_bfloat162 lo = __floats2bfloat162_rn(v.x, v.y);
    __nv_bfloat162 hi = __floats2bfloat162_rn(v.z, v.w);
    uint2 pk = { *reinterpret_cast<uint32_t*>(&lo), *reinterpret_cast<uint32_t*>(&hi) };
    *reinterpret_cast<uint2*>(g_xb + i) = pk;
}

// ---------------------------------------------------------------------------
// Kernel 1: bf16 mma.sync GEMM + argmin. R14 skeleton with d-chunk 64:
// one wait/sync per 64 k-steps (two proven 80B sub-stages per stage).
// ---------------------------------------------------------------------------
__global__ void __launch_bounds__(512, 1)
k_main(const float* __restrict__ cnorm) {
    extern __shared__ char sm[];
    const uint32_t sbase = smem_u32(sm);
    const int tid  = threadIdx.x;
    const int lane = tid & 31, warp = tid >> 5;
    const int wm = warp >> 2, wn = warp & 3;
    const int row0 = blockIdx.x * 128;

    float* scn    = (float*)(sm + SM_CN);
    float* s_pb   = (float*)(sm + SM_PB);
    float* s_ps   = (float*)(sm + SM_PS);
    int*   s_pi   = (int*)  (sm + SM_PI);
    float* s_best = (float*)(sm + SM_BEST);
    float* s_sec  = (float*)(sm + SM_SEC);
    int*   s_bidx = (int*)  (sm + SM_BIDX);

    for (int i = tid; i < K_DIM; i += 512) scn[i] = cnorm[i];
    if (tid < 128) {
        s_best[tid] = __int_as_float(0x7f800000);
        s_sec[tid]  = __int_as_float(0x7f800000);
        s_bidx[tid] = 0;
    }
    __syncthreads();

    // A fill mapping: thread -> (row ar = tid>>2, 8 bf16 at col (tid&3)*8)
    const int ar = tid >> 2, aq = tid & 3;
    const __nv_bfloat16* xb = g_xb + (size_t)(row0 + ar) * D_DIM + aq * 8;
    const uint32_t a_sts = (uint32_t)(ar * 80 + aq * 16);

    // ldmatrix lane base offsets (proven, per sub-stage)
    const uint32_t a_ld = (uint32_t)((wm * 32 + (lane & 15)) * 80 + (lane >> 4) * 16);
    const uint32_t b_ld = (uint32_t)((wn * 64 + (lane & 7) + ((lane & 16) ? 8 : 0)) * 80
                                     + ((lane >> 3) & 1) * 16);

    for (int cc = 0; cc < 4; cc++) {
        const int col0 = cc * 256;
        float acc[2][8][4];
        #pragma unroll
        for (int mt = 0; mt < 2; mt++)
            #pragma unroll
            for (int nt = 0; nt < 8; nt++)
                #pragma unroll
                for (int c = 0; c < 4; c++) acc[mt][nt][c] = 0.f;

        // fill stage buf with d-chunk 64 starting at d0 (both halves, one group)
        auto fill = [&](int d0, int buf) {
            const uint32_t stg = sbase + SM_STG + (uint32_t)buf * STG_BYTES;
            #pragma unroll
            for (int h = 0; h < 2; h++) {
                const uint32_t hs = stg + (uint32_t)h * HALF_BYTES;
                const int dh = d0 + h * 32;
                cpa16(hs + A_HI + a_sts, xb + dh);
                #pragma unroll
                for (int i = 0; i < 2; i++) {
                    int idx = tid + i * 512;
                    int n = idx >> 2, q = idx & 3;
                    cpa16(hs + B_HI + n * 80 + q * 16,
                          g_bhi + (size_t)(col0 + n) * D_DIM + dh + q * 8);
                }
            }
            asm volatile("cp.async.commit_group;");
        };

        // ---- prologue: fill stage 0 ----
        fill(0, 0);

        for (int dc = 0; dc < 12; dc++) {
            const int buf = dc & 1;
            asm volatile("cp.async.wait_group 0;");
            __syncthreads();

            if (dc < 11) fill((dc + 1) * 64, buf ^ 1);

            // ---- compute: 2 halves x 2 k16-steps x 16 mmas ----
            const uint32_t stg = sbase + SM_STG + (uint32_t)buf * STG_BYTES;
            #pragma unroll
            for (int h = 0; h < 2; h++) {
                const uint32_t ab = stg + (uint32_t)h * HALF_BYTES + A_HI + a_ld;
                const uint32_t bb = stg + (uint32_t)h * HALF_BYTES + B_HI + b_ld;
                #pragma unroll
                for (int ks = 0; ks < 2; ks++) {
                    uint32_t afr[2][4];
                    ldsm4(afr[0], ab + ks * 32);
                    ldsm4(afr[1], ab + 1280 + ks * 32);      // +16 rows * 80B
                    uint32_t bfr[4][4];
                    #pragma unroll
                    for (int bt = 0; bt < 4; bt++)
                        ldsm4(bfr[bt], bb + bt * 1280 + ks * 32);
                    #pragma unroll
                    for (int mt = 0; mt < 2; mt++)
                        #pragma unroll
                        for (int nt = 0; nt < 8; nt++)
                            mma16816(acc[mt][nt], afr[mt],
                                     bfr[nt >> 1][(nt & 1) * 2],
                                     bfr[nt >> 1][(nt & 1) * 2 + 1]);
                }
            }
        }

        // ---- epilogue for this 256-col chunk (best + second-best + index) ----
        #pragma unroll
        for (int mt = 0; mt < 2; mt++) {
            #pragma unroll
            for (int h = 0; h < 2; h++) {
                float bv = __int_as_float(0x7f800000);
                float sv = __int_as_float(0x7f800000);
                int bi = 0;
                #pragma unroll
                for (int nt = 0; nt < 8; nt++) {
                    int k0 = col0 + wn * 64 + nt * 8 + (lane & 3) * 2;
                    float v0 = scn[k0]     - 2.0f * acc[mt][nt][h * 2];
                    float v1 = scn[k0 + 1] - 2.0f * acc[mt][nt][h * 2 + 1];
                    if (v0 < bv)      { sv = bv; bv = v0; bi = k0; }
                    else if (v0 < sv) { sv = v0; }
                    if (v1 < bv)      { sv = bv; bv = v1; bi = k0 + 1; }
                    else if (v1 < sv) { sv = v1; }
                }
                #pragma unroll
                for (int m = 1; m <= 2; m <<= 1) {
                    float b2 = __shfl_xor_sync(0xffffffffu, bv, m);
                    float s2 = __shfl_xor_sync(0xffffffffu, sv, m);
                    int   i2 = __shfl_xor_sync(0xffffffffu, bi, m);
                    if (b2 < bv || (b2 == bv && i2 < bi)) {
                        sv = fminf(bv, fminf(sv, s2)); bv = b2; bi = i2;
                    } else {
                        sv = fminf(fminf(sv, s2), b2);
                    }
                }
                if ((lane & 3) == 0) {
                    int row = wm * 32 + mt * 16 + h * 8 + (lane >> 2);
                    s_pb[wn * 128 + row] = bv;
                    s_ps[wn * 128 + row] = sv;
                    s_pi[wn * 128 + row] = bi;
                }
            }
        }
        __syncthreads();
        if (tid < 128) {
            float B = s_pb[tid], S = s_ps[tid]; int I = s_pi[tid];
            #pragma unroll
            for (int w = 1; w < 4; w++) {
                float b2 = s_pb[w * 128 + tid], s2 = s_ps[w * 128 + tid];
                int i2 = s_pi[w * 128 + tid];
                if (b2 < B) { S = fminf(B, fminf(S, s2)); B = b2; I = i2; }
                else        { S = fminf(fminf(S, s2), b2); }
            }
            float rB = s_best[tid], rS = s_sec[tid]; int rI = s_bidx[tid];
            if (B < rB) { rS = fminf(rB, fminf(rS, S)); rB = B; rI = I; }
            else        { rS = fminf(fminf(rS, S), B); }
            s_best[tid] = rB; s_sec[tid] = rS; s_bidx[tid] = rI;
        }
        __syncthreads();
    }

    if (tid < 128) {
        int n = row0 + tid;
        g_idx[n] = s_bidx[tid];
        if (s_sec[tid] - s_best[tid] < FIX_THRESH) {
            int slot = atomicAdd(&g_fix_count, 1);
            if (slot < FIX_CAP) g_fix_rows[slot] = n;
        }
    }
}

// ---------------------------------------------------------------------------
// Kernel 2: batched exact fp32 recheck — 24 flagged rows per C sweep.
// ---------------------------------------------------------------------------
#define FB_ROWS 24
#define FIX_SMEM (FB_ROWS * D_DIM * 4 + 2048)
__global__ void __launch_bounds__(256)
k_fixup2(const float* __restrict__ x, const float* __restrict__ cnorm) {
    extern __shared__ char fsm[];
    float (*s_x)[D_DIM] = (float(*)[D_DIM])fsm;
    float* s_rv = (float*)(fsm + FB_ROWS * D_DIM * 4);
    int*   s_rk = (int*)  (fsm + FB_ROWS * D_DIM * 4 + 1024);
    const int tid = threadIdx.x;
    int cnt = g_fix_count; if (cnt > FIX_CAP) cnt = FIX_CAP;

    for (int base = blockIdx.x * FB_ROWS; base < cnt; base += gridDim.x * FB_ROWS) {
        const int nrows = min(FB_ROWS, cnt - base);
        for (int i = tid; i < nrows * (D_DIM / 4); i += 256) {
            int r = i / (D_DIM / 4), q = i % (D_DIM / 4);
            ((float4*)s_x[r])[q] =
                ((const float4*)(x + (size_t)g_fix_rows[base + r] * D_DIM))[q];
        }
        __syncthreads();

        float best[FB_ROWS]; int bidx[FB_ROWS];
        #pragma unroll
        for (int r = 0; r < FB_ROWS; r++) { best[r] = __int_as_float(0x7f800000); bidx[r] = 0; }

        #pragma unroll 1
        for (int c = 0; c < 4; c++) {
            const int k = tid * 4 + c;
            const float4* cp = (const float4*)(g_ct + (size_t)k * D_DIM);
            const float cn = cnorm[k];
            float acc[FB_ROWS];
            #pragma unroll
            for (int r = 0; r < FB_ROWS; r++) acc[r] = 0.f;
            #pragma unroll 2
            for (int d = 0; d < D_DIM / 4; d++) {
                float4 cv = cp[d];
                #pragma unroll
                for (int r = 0; r < FB_ROWS; r++) {
                    const float* xr = &s_x[r][d * 4];
                    float a = acc[r];
                    a = fmaf(xr[0], cv.x, a); a = fmaf(xr[1], cv.y, a);
                    a = fmaf(xr[2], cv.z, a); a = fmaf(xr[3], cv.w, a);
                    acc[r] = a;
                }
            }
            #pragma unroll
            for (int r = 0; r < FB_ROWS; r++) {
                float val = cn - 2.0f * acc[r];
                if (val < best[r]) { best[r] = val; bidx[r] = k; }
            }
        }

        for (int r = 0; r < nrows; r++) {
            s_rv[tid] = best[r]; s_rk[tid] = bidx[r];
            __syncthreads();
            for (int off = 128; off > 0; off >>= 1) {
                if (tid < off) {
                    if (s_rv[tid + off] < s_rv[tid] ||
                        (s_rv[tid + off] == s_rv[tid] && s_rk[tid + off] < s_rk[tid])) {
                        s_rv[tid] = s_rv[tid + off]; s_rk[tid] = s_rk[tid + off];
                    }
                }
                __syncthreads();
            }
            if (tid == 0) g_idx[g_fix_rows[base + r]] = s_rk[0];
            __syncthreads();
        }
        __syncthreads();
    }
}

// ---------------------------------------------------------------------------
// Kernel 3: gather — out[n,:] = CT[idx[n],:]; 16 rows per block.
// ---------------------------------------------------------------------------
__global__ void k_gather(float* __restrict__ out) {
    const int r0 = blockIdx.x * 16;
    const int t = threadIdx.x;
    #pragma unroll
    for (int r = 0; r < 16; r++) {
        const int n = r0 + r;
        const int k = g_idx[n];
        const float4* src = (const float4*)(g_ct + (size_t)k * D_DIM);
        float4* dst = (float4*)(out + (size_t)n * D_DIM);
        dst[t] = src[t];
    }
}

extern "C" void kernel_launch(void* const* d_in, const int* in_sizes, int n_in,
                              void* d_out, int out_size) {
    const float* x     = (const float*)d_in[0];
    const float* C     = (const float*)d_in[1];
    const float* Cnorm = (const float*)d_in[2];
    float* out = (float*)d_out;

    static bool attr_set = false;
    if (!attr_set) {
        cudaFuncSetAttribute(k_main,   cudaFuncAttributeMaxDynamicSharedMemorySize, SMEM_TOTAL);
        cudaFuncSetAttribute(k_fixup2, cudaFuncAttributeMaxDynamicSharedMemorySize, FIX_SMEM);
        attr_set = true;
    }

    k_prep<<<(K_DIM * D_DIM) / 256, 256>>>(C);
    k_prepx<<<(N_ROWS / 256) * (D_DIM / 4), 256>>>(x);
    k_main<<<N_ROWS / 128, 512, SMEM_TOTAL>>>(Cnorm);
    k_fixup2<<<512, 256, FIX_SMEM>>>(x, Cnorm);
    k_gather<<<N_ROWS / 16, 192>>>(out);
}

// round 16
// speedup vs baseline: 1.0137x; 1.0137x over previous
#include <cuda_runtime.h>
#include <cuda_bf16.h>
#include <cstdint>

#define N_ROWS 262144
#define D_DIM  768
#define K_DIM  1024

// ---------------- device scratch ----------------
__device__ float         g_ct [K_DIM * D_DIM];     // fp32 C^T (gather + exact fixup)
__device__ __nv_bfloat16 g_bhi[K_DIM * D_DIM];     // bf16 C^T (K-major)
__device__ __nv_bfloat16 g_xb [(size_t)N_ROWS * D_DIM];  // bf16 x (402 MB)
__device__ int           g_idx[N_ROWS];
__device__ int           g_fix_count;
__device__ int           g_fix_rows[32768];

// ---------------- helpers ----------------
__device__ __forceinline__ uint32_t smem_u32(const void* p) {
    uint32_t a;
    asm("{ .reg .u64 t; cvta.to.shared.u64 t, %1; cvt.u32.u64 %0, t; }" : "=r"(a) : "l"(p));
    return a;
}
__device__ __forceinline__ void cpa16(uint32_t dst, const void* src) {
    asm volatile("{ .reg .u64 p; cvta.to.global.u64 p, %1; cp.async.cg.shared.global [%0], [p], 16; }"
                 :: "r"(dst), "l"(src));
}
__device__ __forceinline__ void ldsm4(uint32_t* r, uint32_t a) {
    asm volatile("ldmatrix.sync.aligned.m8n8.x4.shared.b16 {%0,%1,%2,%3}, [%4];"
                 : "=r"(r[0]), "=r"(r[1]), "=r"(r[2]), "=r"(r[3]) : "r"(a));
}
__device__ __forceinline__ void mma16816(float* c, const uint32_t* a, uint32_t b0, uint32_t b1) {
    asm volatile("mma.sync.aligned.m16n8k16.row.col.f32.bf16.bf16.f32 "
                 "{%0,%1,%2,%3},{%4,%5,%6,%7},{%8,%9},{%0,%1,%2,%3};"
                 : "+f"(c[0]), "+f"(c[1]), "+f"(c[2]), "+f"(c[3])
                 : "r"(a[0]), "r"(a[1]), "r"(a[2]), "r"(a[3]), "r"(b0), "r"(b1));
}

#define FIX_THRESH 0.87f
#define FIX_CAP    32768

// ---------------- smem layout (dynamic) ----------------
// R8 geometry: 64 rows/CTA, 256 threads, 2 CTAs/SM, 80B padded rows, 2 stages.
#define SM_CN   0        // 1024 f32
#define SM_PB   4096     // 4 x 64 f32 partials
#define SM_PS   5120
#define SM_PI   6144
#define SM_BEST 7168     // 64 f32
#define SM_SEC  7424
#define SM_BIDX 7680
#define SM_STG  8192
#define STG_BYTES 25600  // per stage: A 64x80B + B 256x80B
#define A_HI 0
#define B_HI 5120
#define SMEM_TOTAL (8192 + 2 * 25600)    // 59392 -> 2 CTAs = 118784 B/SM

// ---------------------------------------------------------------------------
// Kernel 0a: C -> fp32 C^T + bf16 C^T; zero fixup counter
// ---------------------------------------------------------------------------
__global__ void k_prep(const float* __restrict__ C) {
    int idx = blockIdx.x * 256 + threadIdx.x;    // idx = d*1024 + k
    if (idx == 0) g_fix_count = 0;
    int d = idx >> 10, k = idx & 1023;
    float v = C[idx];
    size_t o = (size_t)k * D_DIM + d;
    g_ct[o] = v; g_bhi[o] = __float2bfloat16_rn(v);
}

// ---------------------------------------------------------------------------
// Kernel 0b: x -> bf16 (one-time)
// ---------------------------------------------------------------------------
__global__ void k_prepx(const float* __restrict__ x) {
    size_t i = ((size_t)blockIdx.x * 256 + threadIdx.x) * 4;
    float4 v = *(const float4*)(x + i);
    __nv_bfloat162 lo = __floats2bfloat162_rn(v.x, v.y);
    __nv_bfloat162 hi = __floats2bfloat162_rn(v.z, v.w);
    uint2 pk = { *reinterpret_cast<uint32_t*>(&lo), *reinterpret_cast<uint32_t*>(&hi) };
    *reinterpret_cast<uint2*>(g_xb + i) = pk;
}

// ---------------------------------------------------------------------------
// Kernel 1: bf16 mma.sync GEMM + argmin. 64 rows/CTA, 256 threads,
// warp grid 2x4, warp tile 32x64, 2 CTAs/SM, cp.async A+B, 2-stage.
// ---------------------------------------------------------------------------
__global__ void __launch_bounds__(256, 2)
k_main(const float* __restrict__ cnorm) {
    extern __shared__ char sm[];
    const uint32_t sbase = smem_u32(sm);
    const int tid  = threadIdx.x;
    const int lane = tid & 31, warp = tid >> 5;
    const int wm = warp >> 2, wn = warp & 3;      // 2 x 4
    const int row0 = blockIdx.x * 64;

    float* scn    = (float*)(sm + SM_CN);
    float* s_pb   = (float*)(sm + SM_PB);
    float* s_ps   = (float*)(sm + SM_PS);
    int*   s_pi   = (int*)  (sm + SM_PI);
    float* s_best = (float*)(sm + SM_BEST);
    float* s_sec  = (float*)(sm + SM_SEC);
    int*   s_bidx = (int*)  (sm + SM_BIDX);

    for (int i = tid; i < K_DIM; i += 256) scn[i] = cnorm[i];
    if (tid < 64) {
        s_best[tid] = __int_as_float(0x7f800000);
        s_sec[tid]  = __int_as_float(0x7f800000);
        s_bidx[tid] = 0;
    }
    __syncthreads();

    // A fill mapping: thread -> (row ar = tid>>2 in 0..63, 8 bf16 at (tid&3)*8)
    const int ar = tid >> 2, aq = tid & 3;
    const __nv_bfloat16* xb = g_xb + (size_t)(row0 + ar) * D_DIM + aq * 8;
    const uint32_t a_sts = (uint32_t)(ar * 80 + aq * 16);

    // ldmatrix lane base offsets (proven)
    const uint32_t a_ld = (uint32_t)((wm * 32 + (lane & 15)) * 80 + (lane >> 4) * 16);
    const uint32_t b_ld = (uint32_t)((wn * 64 + (lane & 7) + ((lane & 16) ? 8 : 0)) * 80
                                     + ((lane >> 3) & 1) * 16);

    for (int cc = 0; cc < 4; cc++) {
        const int col0 = cc * 256;
        float acc[2][8][4];
        #pragma unroll
        for (int mt = 0; mt < 2; mt++)
            #pragma unroll
            for (int nt = 0; nt < 8; nt++)
                #pragma unroll
                for (int c = 0; c < 4; c++) acc[mt][nt][c] = 0.f;

        // fill A+B for d-offset d0 into stage buffer, one commit group
        auto fill = [&](int d0, int buf) {
            const uint32_t stg = sbase + SM_STG + (uint32_t)buf * STG_BYTES;
            cpa16(stg + A_HI + a_sts, xb + d0);
            #pragma unroll
            for (int i = 0; i < 4; i++) {
                int idx = tid + i * 256;
                int n = idx >> 2, q = idx & 3;
                cpa16(stg + B_HI + n * 80 + q * 16,
                      g_bhi + (size_t)(col0 + n) * D_DIM + d0 + q * 8);
            }
            asm volatile("cp.async.commit_group;");
        };

        // ---- prologue: fill stage 0 ----
        fill(0, 0);

        for (int dc = 0; dc < 24; dc++) {
            const int buf = dc & 1;
            asm volatile("cp.async.wait_group 0;");
            __syncthreads();

            if (dc < 23) fill((dc + 1) * 32, buf ^ 1);

            // ---- compute: 2 k16-steps x 16 mmas ----
            const uint32_t stg = sbase + SM_STG + (uint32_t)buf * STG_BYTES;
            const uint32_t ab = stg + A_HI + a_ld;
            const uint32_t bb = stg + B_HI + b_ld;
            #pragma unroll
            for (int ks = 0; ks < 2; ks++) {
                uint32_t afr[2][4];
                ldsm4(afr[0], ab + ks * 32);
                ldsm4(afr[1], ab + 1280 + ks * 32);          // +16 rows * 80B
                uint32_t bfr[4][4];
                #pragma unroll
                for (int bt = 0; bt < 4; bt++)
                    ldsm4(bfr[bt], bb + bt * 1280 + ks * 32);
                #pragma unroll
                for (int mt = 0; mt < 2; mt++)
                    #pragma unroll
                    for (int nt = 0; nt < 8; nt++)
                        mma16816(acc[mt][nt], afr[mt],
                                 bfr[nt >> 1][(nt & 1) * 2],
                                 bfr[nt >> 1][(nt & 1) * 2 + 1]);
            }
        }

        // ---- epilogue for this 256-col chunk (best + second + index) ----
        #pragma unroll
        for (int mt = 0; mt < 2; mt++) {
            #pragma unroll
            for (int h = 0; h < 2; h++) {
                float bv = __int_as_float(0x7f800000);
                float sv = __int_as_float(0x7f800000);
                int bi = 0;
                #pragma unroll
                for (int nt = 0; nt < 8; nt++) {
                    int k0 = col0 + wn * 64 + nt * 8 + (lane & 3) * 2;
                    float v0 = scn[k0]     - 2.0f * acc[mt][nt][h * 2];
                    float v1 = scn[k0 + 1] - 2.0f * acc[mt][nt][h * 2 + 1];
                    if (v0 < bv)      { sv = bv; bv = v0; bi = k0; }
                    else if (v0 < sv) { sv = v0; }
                    if (v1 < bv)      { sv = bv; bv = v1; bi = k0 + 1; }
                    else if (v1 < sv) { sv = v1; }
                }
                #pragma unroll
                for (int m = 1; m <= 2; m <<= 1) {
                    float b2 = __shfl_xor_sync(0xffffffffu, bv, m);
                    float s2 = __shfl_xor_sync(0xffffffffu, sv, m);
                    int   i2 = __shfl_xor_sync(0xffffffffu, bi, m);
                    if (b2 < bv || (b2 == bv && i2 < bi)) {
                        sv = fminf(bv, fminf(sv, s2)); bv = b2; bi = i2;
                    } else {
                        sv = fminf(fminf(sv, s2), b2);
                    }
                }
                if ((lane & 3) == 0) {
                    int row = wm * 32 + mt * 16 + h * 8 + (lane >> 2);   // 0..63
                    s_pb[wn * 64 + row] = bv;
                    s_ps[wn * 64 + row] = sv;
                    s_pi[wn * 64 + row] = bi;
                }
            }
        }
        __syncthreads();
        if (tid < 64) {
            float B = s_pb[tid], S = s_ps[tid]; int I = s_pi[tid];
            #pragma unroll
            for (int w = 1; w < 4; w++) {
                float b2 = s_pb[w * 64 + tid], s2 = s_ps[w * 64 + tid];
                int i2 = s_pi[w * 64 + tid];
                if (b2 < B) { S = fminf(B, fminf(S, s2)); B = b2; I = i2; }
                else        { S = fminf(fminf(S, s2), b2); }
            }
            float rB = s_best[tid], rS = s_sec[tid]; int rI = s_bidx[tid];
            if (B < rB) { rS = fminf(rB, fminf(rS, S)); rB = B; rI = I; }
            else        { rS = fminf(fminf(rS, S), B); }
            s_best[tid] = rB; s_sec[tid] = rS; s_bidx[tid] = rI;
        }
        __syncthreads();
    }

    if (tid < 64) {
        int n = row0 + tid;
        g_idx[n] = s_bidx[tid];
        if (s_sec[tid] - s_best[tid] < FIX_THRESH) {
            int slot = atomicAdd(&g_fix_count, 1);
            if (slot < FIX_CAP) g_fix_rows[slot] = n;
        }
    }
}

// ---------------------------------------------------------------------------
// Kernel 2: batched exact fp32 recheck — 24 flagged rows per C sweep.
// ---------------------------------------------------------------------------
#define FB_ROWS 24
#define FIX_SMEM (FB_ROWS * D_DIM * 4 + 2048)
__global__ void __launch_bounds__(256)
k_fixup2(const float* __restrict__ x, const float* __restrict__ cnorm) {
    extern __shared__ char fsm[];
    float (*s_x)[D_DIM] = (float(*)[D_DIM])fsm;
    float* s_rv = (float*)(fsm + FB_ROWS * D_DIM * 4);
    int*   s_rk = (int*)  (fsm + FB_ROWS * D_DIM * 4 + 1024);
    const int tid = threadIdx.x;
    int cnt = g_fix_count; if (cnt > FIX_CAP) cnt = FIX_CAP;

    for (int base = blockIdx.x * FB_ROWS; base < cnt; base += gridDim.x * FB_ROWS) {
        const int nrows = min(FB_ROWS, cnt - base);
        for (int i = tid; i < nrows * (D_DIM / 4); i += 256) {
            int r = i / (D_DIM / 4), q = i % (D_DIM / 4);
            ((float4*)s_x[r])[q] =
                ((const float4*)(x + (size_t)g_fix_rows[base + r] * D_DIM))[q];
        }
        __syncthreads();

        float best[FB_ROWS]; int bidx[FB_ROWS];
        #pragma unroll
        for (int r = 0; r < FB_ROWS; r++) { best[r] = __int_as_float(0x7f800000); bidx[r] = 0; }

        #pragma unroll 1
        for (int c = 0; c < 4; c++) {
            const int k = tid * 4 + c;
            const float4* cp = (const float4*)(g_ct + (size_t)k * D_DIM);
            const float cn = cnorm[k];
            float acc[FB_ROWS];
            #pragma unroll
            for (int r = 0; r < FB_ROWS; r++) acc[r] = 0.f;
            #pragma unroll 2
            for (int d = 0; d < D_DIM / 4; d++) {
                float4 cv = cp[d];
                #pragma unroll
                for (int r = 0; r < FB_ROWS; r++) {
                    const float* xr = &s_x[r][d * 4];
                    float a = acc[r];
                    a = fmaf(xr[0], cv.x, a); a = fmaf(xr[1], cv.y, a);
                    a = fmaf(xr[2], cv.z, a); a = fmaf(xr[3], cv.w, a);
                    acc[r] = a;
                }
            }
            #pragma unroll
            for (int r = 0; r < FB_ROWS; r++) {
                float val = cn - 2.0f * acc[r];
                if (val < best[r]) { best[r] = val; bidx[r] = k; }
            }
        }

        for (int r = 0; r < nrows; r++) {
            s_rv[tid] = best[r]; s_rk[tid] = bidx[r];
            __syncthreads();
            for (int off = 128; off > 0; off >>= 1) {
                if (tid < off) {
                    if (s_rv[tid + off] < s_rv[tid] ||
                        (s_rv[tid + off] == s_rv[tid] && s_rk[tid + off] < s_rk[tid])) {
                        s_rv[tid] = s_rv[tid + off]; s_rk[tid] = s_rk[tid + off];
                    }
                }
                __syncthreads();
            }
            if (tid == 0) g_idx[g_fix_rows[base + r]] = s_rk[0];
            __syncthreads();
        }
        __syncthreads();
    }
}

// ---------------------------------------------------------------------------
// Kernel 3: gather — out[n,:] = CT[idx[n],:]; 16 rows per block.
// ---------------------------------------------------------------------------
__global__ void k_gather(float* __restrict__ out) {
    const int r0 = blockIdx.x * 16;
    const int t = threadIdx.x;
    #pragma unroll
    for (int r = 0; r < 16; r++) {
        const int n = r0 + r;
        const int k = g_idx[n];
        const float4* src = (const float4*)(g_ct + (size_t)k * D_DIM);
        float4* dst = (float4*)(out + (size_t)n * D_DIM);
        dst[t] = src[t];
    }
}

extern "C" void kernel_launch(void* const* d_in, const int* in_sizes, int n_in,
                              void* d_out, int out_size) {
    const float* x     = (const float*)d_in[0];
    const float* C     = (const float*)d_in[1];
    const float* Cnorm = (const float*)d_in[2];
    float* out = (float*)d_out;

    static bool attr_set = false;
    if (!attr_set) {
        cudaFuncSetAttribute(k_main,   cudaFuncAttributeMaxDynamicSharedMemorySize, SMEM_TOTAL);
        cudaFuncSetAttribute(k_fixup2, cudaFuncAttributeMaxDynamicSharedMemorySize, FIX_SMEM);
        attr_set = true;
    }

    k_prep<<<(K_DIM * D_DIM) / 256, 256>>>(C);
    k_prepx<<<(N_ROWS / 256) * (D_DIM / 4), 256>>>(x);
    k_main<<<N_ROWS / 64, 256, SMEM_TOTAL>>>(Cnorm);
    k_fixup2<<<512, 256, FIX_SMEM>>>(x, Cnorm);
    k_gather<<<N_ROWS / 16, 192>>>(out);
}